// round 2
// baseline (speedup 1.0000x reference)
#include <cuda_runtime.h>

#define D      256
#define NB     30
#define EPG    240
#define NGRAPH 2048
#define NE     (NGRAPH * EPG)
#define NSEM   11
#define VH     15      // node rows per thread-half

// ---------------- device scratch (no allocation allowed) ----------------
static __device__ float d_Wg2[5 * D];        // W_geo @ W_lot[0:256]
static __device__ float d_biasA[D];          // b_geo @ W_lot[0:256] + b_lot
static __device__ float d_tab2[NSEM * D];    // emb @ W_lot[256:512]
static __device__ float d_gcat[NGRAPH * 4 * D];  // [g0|g1|g2|g3] per graph

// ---------------- packed f32x2 helpers ----------------
__device__ __forceinline__ unsigned long long pk2(float lo, float hi) {
    unsigned long long r;
    asm("mov.b64 %0,{%1,%2};" : "=l"(r) : "f"(lo), "f"(hi));
    return r;
}
__device__ __forceinline__ void upk2(unsigned long long p, float& lo, float& hi) {
    asm("mov.b64 {%0,%1},%2;" : "=f"(lo), "=f"(hi) : "l"(p));
}
__device__ __forceinline__ unsigned long long ffma2(unsigned long long a,
                                                    unsigned long long b,
                                                    unsigned long long c) {
    unsigned long long d_;
    asm("fma.rn.f32x2 %0,%1,%2,%3;" : "=l"(d_) : "l"(a), "l"(b), "l"(c));
    return d_;
}

// ---------------- precompute: fold encoder weights ----------------
__global__ void precompute_kernel(const float* __restrict__ Wgeo,
                                  const float* __restrict__ bgeo,
                                  const float* __restrict__ emb,
                                  const float* __restrict__ Wlot,
                                  const float* __restrict__ blot) {
    const int r = blockIdx.x, t = threadIdx.x;
    float acc = 0.f;
    if (r < 5) {
        #pragma unroll 8
        for (int k = 0; k < D; k++) acc = fmaf(Wgeo[r * D + k], Wlot[k * D + t], acc);
        d_Wg2[r * D + t] = acc;
    } else if (r == 5) {
        #pragma unroll 8
        for (int k = 0; k < D; k++) acc = fmaf(bgeo[k], Wlot[k * D + t], acc);
        d_biasA[t] = acc + blot[t];
    } else {
        const int s = r - 6;
        #pragma unroll 8
        for (int k = 0; k < D; k++) acc = fmaf(emb[s * D + k], Wlot[(D + k) * D + t], acc);
        d_tab2[s * D + t] = acc;
    }
}

// ---------------- main fused kernel: one CTA (512 thr) per graph ----------------
// SMEM layout (floats):
#define SM_H    0        // h[30][256]
#define SM_A    7680     // half0 partial agg [30][256] -> combined agg
#define SM_A2   15360    // half1 partial agg [30][256]
#define SM_INV  23040    // inv count [30] (+2 pad)
#define SM_GEO  23072    // geometry [30*5] (+10 pad)
#define SM_SEM  23232    // semantic ints [30] (+2)
#define SM_ES   23264    // local src [240]
#define SM_ED   23504    // local dst [240]
#define SM_TMP  23744    // colmax combine [512]
#define SM_FLOATS 24256  // 97024 bytes

__global__ __launch_bounds__(512, 1)
void gnn_main(const float* __restrict__ geometry, const int* __restrict__ semantic,
              const int* __restrict__ esrc_g, const int* __restrict__ edst_g,
              const float* __restrict__ Wlot,
              const float* __restrict__ W1, const float* __restrict__ b1,
              const float* __restrict__ W2, const float* __restrict__ b2,
              const float* __restrict__ W3, const float* __restrict__ b3) {
    extern __shared__ float smem[];
    const int b  = blockIdx.x, t = threadIdx.x;
    const int col = t & 255;
    const int hf  = t >> 8;         // which thread-half
    const int vb  = hf * VH;        // first node row owned by this half

    float* sh_h   = smem + SM_H;
    float* sh_a   = smem + SM_A;
    float* sh_a2  = smem + SM_A2;
    float* sh_inv = smem + SM_INV;
    float* sh_geo = smem + SM_GEO;
    int*   sh_sem = (int*)(smem + SM_SEM);
    int*   sh_es  = (int*)(smem + SM_ES);
    int*   sh_ed  = (int*)(smem + SM_ED);
    float* sh_tmp = smem + SM_TMP;

    // ---- load per-graph metadata ----
    if (t < NB) { sh_inv[t] = 0.f; sh_sem[t] = semantic[b * NB + t]; }
    if (t < EPG) {
        sh_es[t] = esrc_g[b * EPG + t] - b * NB;
        sh_ed[t] = edst_g[b * EPG + t] - b * NB;
    }
    if (t < NB * 5) sh_geo[t] = geometry[b * NB * 5 + t];
    __syncthreads();
    if (t < EPG) atomicAdd(&sh_inv[sh_ed[t]], 1.0f);
    __syncthreads();
    if (t < NB) { float c = sh_inv[t]; sh_inv[t] = (c > 0.f) ? (1.0f / c) : 0.f; }

    // ---- phase 1: h0 = relu(geo@Wg2 + tab2[sem] + W_lot[512+v] + biasA); g0 = colmax ----
    {
        float m = 0.f;
        const float ba = d_biasA[col];
        #pragma unroll
        for (int vv = 0; vv < VH; vv++) {
            const int v = vb + vv;
            float acc = ba + d_tab2[sh_sem[v] * D + col] + Wlot[(2 * D + v) * D + col];
            #pragma unroll
            for (int j = 0; j < 5; j++)
                acc = fmaf(sh_geo[v * 5 + j], d_Wg2[j * D + col], acc);
            acc = fmaxf(acc, 0.f);
            sh_h[v * D + col] = acc;
            m = fmaxf(m, acc);
        }
        sh_tmp[t] = m;
    }
    __syncthreads();
    if (t < 256) d_gcat[b * (4 * D) + t] = fmaxf(sh_tmp[t], sh_tmp[t + 256]);

    // ---- 3 message-passing layers ----
    const float* Ws[3] = {W1, W2, W3};
    const float* bs[3] = {b1, b2, b3};

    for (int L = 0; L < 3; ++L) {
        // each half aggregates its 120 edges into its private buffer (col-exclusive)
        float* myA = hf ? sh_a2 : sh_a;
        #pragma unroll
        for (int v = 0; v < NB; v++) myA[v * D + col] = 0.f;
        const int e0 = hf * (EPG / 2);
        #pragma unroll 4
        for (int e = 0; e < EPG / 2; e++) {
            const int s_ = sh_es[e0 + e], dd = sh_ed[e0 + e];
            myA[dd * D + col] += sh_h[s_ * D + col];
        }
        __syncthreads();
        // combine partials + scale by 1/cnt (each half handles its own rows)
        #pragma unroll
        for (int vv = 0; vv < VH; vv++) {
            const int v = vb + vv;
            sh_a[v * D + col] = (sh_a[v * D + col] + sh_a2[v * D + col]) * sh_inv[v];
        }
        __syncthreads();

        // GEMM: acc[v] = h[v]@W_top[:,col] + agg[v]@W_bot[:,col], f32x2 packed
        unsigned long long acc2[VH];
        #pragma unroll
        for (int vv = 0; vv < VH; vv++) acc2[vv] = 0ULL;
        const float* Wc = Ws[L] + col;

        #pragma unroll 2
        for (int k = 0; k < D; k += 4) {
            const unsigned long long w01 = pk2(Wc[(k    ) * D], Wc[(k + 1) * D]);
            const unsigned long long w23 = pk2(Wc[(k + 2) * D], Wc[(k + 3) * D]);
            #pragma unroll
            for (int vv = 0; vv < VH; vv++) {
                const ulonglong2 x = *(const ulonglong2*)(sh_h + (vb + vv) * D + k);
                acc2[vv] = ffma2(x.x, w01, acc2[vv]);
                acc2[vv] = ffma2(x.y, w23, acc2[vv]);
            }
        }
        const float* Wc2 = Wc + D * D;
        #pragma unroll 2
        for (int k = 0; k < D; k += 4) {
            const unsigned long long w01 = pk2(Wc2[(k    ) * D], Wc2[(k + 1) * D]);
            const unsigned long long w23 = pk2(Wc2[(k + 2) * D], Wc2[(k + 3) * D]);
            #pragma unroll
            for (int vv = 0; vv < VH; vv++) {
                const ulonglong2 x = *(const ulonglong2*)(sh_a + (vb + vv) * D + k);
                acc2[vv] = ffma2(x.x, w01, acc2[vv]);
                acc2[vv] = ffma2(x.y, w23, acc2[vv]);
            }
        }

        const float bias = bs[L][col];
        __syncthreads();  // all GEMM reads of sh_h/sh_a complete before overwrite
        float m = 0.f;
        #pragma unroll
        for (int vv = 0; vv < VH; vv++) {
            const int v = vb + vv;
            float lo, hi; upk2(acc2[vv], lo, hi);
            float val = lo + hi + bias;
            val = fmaxf(val, 0.f);
            val = (sh_inv[v] > 0.f) ? val : 0.f;  // cnt==0 -> exactly 0
            sh_h[v * D + col] = val;
            m = fmaxf(m, val);
        }
        sh_tmp[t] = m;
        __syncthreads();
        if (t < 256)
            d_gcat[b * (4 * D) + (L + 1) * D + t] = fmaxf(sh_tmp[t], sh_tmp[t + 256]);
    }
}

// ---------------- head: latent = g@W_agg+b; mu/logvar. 16 graphs per CTA ----------------
#define GPB 16
__global__ __launch_bounds__(256, 2)
void head_kernel(const float* __restrict__ Wagg, const float* __restrict__ bagg,
                 const float* __restrict__ Wmu, const float* __restrict__ bmu,
                 const float* __restrict__ Wvar, const float* __restrict__ bvar,
                 float* __restrict__ out) {
    extern __shared__ float smem[];
    float* sg   = smem;                // [GPB][1024]
    float* slat = smem + GPB * 1024;   // [GPB][256]
    const int t = threadIdx.x;
    const int b0 = blockIdx.x * GPB;

    for (int i = t; i < GPB * 1024; i += 256) sg[i] = d_gcat[b0 * 1024 + i];
    __syncthreads();

    // latent = g @ W_agg + b_agg  (packed over k)
    unsigned long long acc2[GPB];
    #pragma unroll
    for (int g = 0; g < GPB; g++) acc2[g] = 0ULL;
    #pragma unroll 2
    for (int k = 0; k < 1024; k += 2) {
        const unsigned long long w2 = pk2(Wagg[k * D + t], Wagg[(k + 1) * D + t]);
        #pragma unroll
        for (int g = 0; g < GPB; g++) {
            const unsigned long long x = *(const unsigned long long*)(sg + g * 1024 + k);
            acc2[g] = ffma2(x, w2, acc2[g]);
        }
    }
    {
        const float ba = bagg[t];
        #pragma unroll
        for (int g = 0; g < GPB; g++) {
            float lo, hi; upk2(acc2[g], lo, hi);
            slat[g * D + t] = lo + hi + ba;
        }
    }
    __syncthreads();

    // mu / log_var (packed over k)
    unsigned long long mu2[GPB], lv2[GPB];
    #pragma unroll
    for (int g = 0; g < GPB; g++) { mu2[g] = 0ULL; lv2[g] = 0ULL; }
    #pragma unroll 2
    for (int k = 0; k < D; k += 2) {
        const unsigned long long wm = pk2(Wmu[k * D + t],  Wmu[(k + 1) * D + t]);
        const unsigned long long wv = pk2(Wvar[k * D + t], Wvar[(k + 1) * D + t]);
        #pragma unroll
        for (int g = 0; g < GPB; g++) {
            const unsigned long long x = *(const unsigned long long*)(slat + g * D + k);
            mu2[g] = ffma2(x, wm, mu2[g]);
            lv2[g] = ffma2(x, wv, lv2[g]);
        }
    }
    const float bm = bmu[t], bv = bvar[t];
    #pragma unroll
    for (int g = 0; g < GPB; g++) {
        float lo, hi; upk2(mu2[g], lo, hi);
        out[(b0 + g) * D + t] = lo + hi + bm;
        upk2(lv2[g], lo, hi);
        out[NGRAPH * D + (b0 + g) * D + t] = lo + hi + bv;
    }
}

// ---------------- launch ----------------
extern "C" void kernel_launch(void* const* d_in, const int* in_sizes, int n_in,
                              void* d_out, int out_size) {
    (void)in_sizes; (void)n_in; (void)out_size;
    const float* geometry   = (const float*)d_in[0];
    const int*   semantic   = (const int*)  d_in[1];
    const int*   edge_index = (const int*)  d_in[2];
    // d_in[3] = batch (unused: nodes contiguous per graph)
    const float* W_geo = (const float*)d_in[4];
    const float* b_geo = (const float*)d_in[5];
    const float* emb   = (const float*)d_in[6];
    const float* W_lot = (const float*)d_in[7];
    const float* b_lot = (const float*)d_in[8];
    const float* W1    = (const float*)d_in[9];
    const float* b1    = (const float*)d_in[10];
    const float* W2    = (const float*)d_in[11];
    const float* b2    = (const float*)d_in[12];
    const float* W3    = (const float*)d_in[13];
    const float* b3    = (const float*)d_in[14];
    const float* W_agg = (const float*)d_in[15];
    const float* b_agg = (const float*)d_in[16];
    const float* W_mu  = (const float*)d_in[17];
    const float* b_mu  = (const float*)d_in[18];
    const float* W_var = (const float*)d_in[19];
    const float* b_var = (const float*)d_in[20];

    const size_t smem_main = SM_FLOATS * sizeof(float);                   // 97024 B
    const size_t smem_head = (GPB * 1024 + GPB * 256) * sizeof(float);    // 81920 B
    cudaFuncSetAttribute((const void*)gnn_main,
                         cudaFuncAttributeMaxDynamicSharedMemorySize, (int)smem_main);
    cudaFuncSetAttribute((const void*)head_kernel,
                         cudaFuncAttributeMaxDynamicSharedMemorySize, (int)smem_head);

    precompute_kernel<<<17, 256>>>(W_geo, b_geo, emb, W_lot, b_lot);
    gnn_main<<<NGRAPH, 512, smem_main>>>(geometry, semantic,
                                         edge_index, edge_index + NE,
                                         W_lot, W1, b1, W2, b2, W3, b3);
    head_kernel<<<NGRAPH / GPB, 256, smem_head>>>(W_agg, b_agg, W_mu, b_mu,
                                                  W_var, b_var, (float*)d_out);
}

// round 3
// speedup vs baseline: 1.0003x; 1.0003x over previous
#include <cuda_runtime.h>

#define D      256
#define NB     30
#define EPG    240
#define NGRAPH 2048
#define NE     (NGRAPH * EPG)
#define NSEM   11
#define VH     15      // node rows per thread-half

// ---------------- device scratch (no allocation allowed) ----------------
static __device__ float d_Wg2[5 * D];        // W_geo @ W_lot[0:256]
static __device__ float d_biasA[D];          // b_geo @ W_lot[0:256] + b_lot
static __device__ float d_tab2[NSEM * D];    // emb @ W_lot[256:512]
static __device__ float d_gcat[NGRAPH * 4 * D];  // [g0|g1|g2|g3] per graph

// ---------------- packed f32x2 helpers ----------------
__device__ __forceinline__ unsigned long long pk2(float lo, float hi) {
    unsigned long long r;
    asm("mov.b64 %0,{%1,%2};" : "=l"(r) : "f"(lo), "f"(hi));
    return r;
}
__device__ __forceinline__ void upk2(unsigned long long p, float& lo, float& hi) {
    asm("mov.b64 {%0,%1},%2;" : "=f"(lo), "=f"(hi) : "l"(p));
}
__device__ __forceinline__ unsigned long long ffma2(unsigned long long a,
                                                    unsigned long long b,
                                                    unsigned long long c) {
    unsigned long long d_;
    asm("fma.rn.f32x2 %0,%1,%2,%3;" : "=l"(d_) : "l"(a), "l"(b), "l"(c));
    return d_;
}

// ---------------- precompute: fold encoder weights ----------------
__global__ void precompute_kernel(const float* __restrict__ Wgeo,
                                  const float* __restrict__ bgeo,
                                  const float* __restrict__ emb,
                                  const float* __restrict__ Wlot,
                                  const float* __restrict__ blot) {
    const int r = blockIdx.x, t = threadIdx.x;
    float acc = 0.f;
    if (r < 5) {
        #pragma unroll 8
        for (int k = 0; k < D; k++) acc = fmaf(Wgeo[r * D + k], Wlot[k * D + t], acc);
        d_Wg2[r * D + t] = acc;
    } else if (r == 5) {
        #pragma unroll 8
        for (int k = 0; k < D; k++) acc = fmaf(bgeo[k], Wlot[k * D + t], acc);
        d_biasA[t] = acc + blot[t];
    } else {
        const int s = r - 6;
        #pragma unroll 8
        for (int k = 0; k < D; k++) acc = fmaf(emb[s * D + k], Wlot[(D + k) * D + t], acc);
        d_tab2[s * D + t] = acc;
    }
}

// ---------------- main fused kernel: one CTA (512 thr) per graph ----------------
// SMEM layout (floats):
#define SM_H    0        // h[30][256]
#define SM_A    7680     // half0 partial agg [30][256] -> combined agg
#define SM_A2   15360    // half1 partial agg [30][256]
#define SM_INV  23040    // inv count [30] (+2 pad)
#define SM_GEO  23072    // geometry [30*5] (+10 pad)
#define SM_SEM  23232    // semantic ints [30] (+2)
#define SM_ES   23264    // local src [240]
#define SM_ED   23504    // local dst [240]
#define SM_TMP  23744    // colmax combine [512]
#define SM_FLOATS 24256  // 97024 bytes

__global__ __launch_bounds__(512, 1)
void gnn_main(const float* __restrict__ geometry, const int* __restrict__ semantic,
              const int* __restrict__ esrc_g, const int* __restrict__ edst_g,
              const float* __restrict__ Wlot,
              const float* __restrict__ W1, const float* __restrict__ b1,
              const float* __restrict__ W2, const float* __restrict__ b2,
              const float* __restrict__ W3, const float* __restrict__ b3) {
    extern __shared__ float smem[];
    const int b  = blockIdx.x, t = threadIdx.x;
    const int col = t & 255;
    const int hf  = t >> 8;         // which thread-half
    const int vb  = hf * VH;        // first node row owned by this half

    float* sh_h   = smem + SM_H;
    float* sh_a   = smem + SM_A;
    float* sh_a2  = smem + SM_A2;
    float* sh_inv = smem + SM_INV;
    float* sh_geo = smem + SM_GEO;
    int*   sh_sem = (int*)(smem + SM_SEM);
    int*   sh_es  = (int*)(smem + SM_ES);
    int*   sh_ed  = (int*)(smem + SM_ED);
    float* sh_tmp = smem + SM_TMP;

    // ---- load per-graph metadata ----
    if (t < NB) { sh_inv[t] = 0.f; sh_sem[t] = semantic[b * NB + t]; }
    if (t < EPG) {
        sh_es[t] = esrc_g[b * EPG + t] - b * NB;
        sh_ed[t] = edst_g[b * EPG + t] - b * NB;
    }
    if (t < NB * 5) sh_geo[t] = geometry[b * NB * 5 + t];
    __syncthreads();
    if (t < EPG) atomicAdd(&sh_inv[sh_ed[t]], 1.0f);
    __syncthreads();
    if (t < NB) { float c = sh_inv[t]; sh_inv[t] = (c > 0.f) ? (1.0f / c) : 0.f; }

    // ---- phase 1: h0 = relu(geo@Wg2 + tab2[sem] + W_lot[512+v] + biasA); g0 = colmax ----
    {
        float m = 0.f;
        const float ba = d_biasA[col];
        #pragma unroll
        for (int vv = 0; vv < VH; vv++) {
            const int v = vb + vv;
            float acc = ba + d_tab2[sh_sem[v] * D + col] + Wlot[(2 * D + v) * D + col];
            #pragma unroll
            for (int j = 0; j < 5; j++)
                acc = fmaf(sh_geo[v * 5 + j], d_Wg2[j * D + col], acc);
            acc = fmaxf(acc, 0.f);
            sh_h[v * D + col] = acc;
            m = fmaxf(m, acc);
        }
        sh_tmp[t] = m;
    }
    __syncthreads();
    if (t < 256) d_gcat[b * (4 * D) + t] = fmaxf(sh_tmp[t], sh_tmp[t + 256]);

    // ---- 3 message-passing layers ----
    const float* Ws[3] = {W1, W2, W3};
    const float* bs[3] = {b1, b2, b3};

    for (int L = 0; L < 3; ++L) {
        // each half aggregates its 120 edges into its private buffer (col-exclusive)
        float* myA = hf ? sh_a2 : sh_a;
        #pragma unroll
        for (int v = 0; v < NB; v++) myA[v * D + col] = 0.f;
        const int e0 = hf * (EPG / 2);
        #pragma unroll 4
        for (int e = 0; e < EPG / 2; e++) {
            const int s_ = sh_es[e0 + e], dd = sh_ed[e0 + e];
            myA[dd * D + col] += sh_h[s_ * D + col];
        }
        __syncthreads();
        // combine partials + scale by 1/cnt (each half handles its own rows)
        #pragma unroll
        for (int vv = 0; vv < VH; vv++) {
            const int v = vb + vv;
            sh_a[v * D + col] = (sh_a[v * D + col] + sh_a2[v * D + col]) * sh_inv[v];
        }
        __syncthreads();

        // GEMM: acc[v] = h[v]@W_top[:,col] + agg[v]@W_bot[:,col], f32x2 packed
        unsigned long long acc2[VH];
        #pragma unroll
        for (int vv = 0; vv < VH; vv++) acc2[vv] = 0ULL;
        const float* Wc = Ws[L] + col;

        #pragma unroll 2
        for (int k = 0; k < D; k += 4) {
            const unsigned long long w01 = pk2(Wc[(k    ) * D], Wc[(k + 1) * D]);
            const unsigned long long w23 = pk2(Wc[(k + 2) * D], Wc[(k + 3) * D]);
            #pragma unroll
            for (int vv = 0; vv < VH; vv++) {
                const ulonglong2 x = *(const ulonglong2*)(sh_h + (vb + vv) * D + k);
                acc2[vv] = ffma2(x.x, w01, acc2[vv]);
                acc2[vv] = ffma2(x.y, w23, acc2[vv]);
            }
        }
        const float* Wc2 = Wc + D * D;
        #pragma unroll 2
        for (int k = 0; k < D; k += 4) {
            const unsigned long long w01 = pk2(Wc2[(k    ) * D], Wc2[(k + 1) * D]);
            const unsigned long long w23 = pk2(Wc2[(k + 2) * D], Wc2[(k + 3) * D]);
            #pragma unroll
            for (int vv = 0; vv < VH; vv++) {
                const ulonglong2 x = *(const ulonglong2*)(sh_a + (vb + vv) * D + k);
                acc2[vv] = ffma2(x.x, w01, acc2[vv]);
                acc2[vv] = ffma2(x.y, w23, acc2[vv]);
            }
        }

        const float bias = bs[L][col];
        __syncthreads();  // all GEMM reads of sh_h/sh_a complete before overwrite
        float m = 0.f;
        #pragma unroll
        for (int vv = 0; vv < VH; vv++) {
            const int v = vb + vv;
            float lo, hi; upk2(acc2[vv], lo, hi);
            float val = lo + hi + bias;
            val = fmaxf(val, 0.f);
            val = (sh_inv[v] > 0.f) ? val : 0.f;  // cnt==0 -> exactly 0
            sh_h[v * D + col] = val;
            m = fmaxf(m, val);
        }
        sh_tmp[t] = m;
        __syncthreads();
        if (t < 256)
            d_gcat[b * (4 * D) + (L + 1) * D + t] = fmaxf(sh_tmp[t], sh_tmp[t + 256]);
    }
}

// ---------------- head: latent = g@W_agg+b; mu/logvar. 16 graphs per CTA ----------------
#define GPB 16
__global__ __launch_bounds__(256, 2)
void head_kernel(const float* __restrict__ Wagg, const float* __restrict__ bagg,
                 const float* __restrict__ Wmu, const float* __restrict__ bmu,
                 const float* __restrict__ Wvar, const float* __restrict__ bvar,
                 float* __restrict__ out) {
    extern __shared__ float smem[];
    float* sg   = smem;                // [GPB][1024]
    float* slat = smem + GPB * 1024;   // [GPB][256]
    const int t = threadIdx.x;
    const int b0 = blockIdx.x * GPB;

    for (int i = t; i < GPB * 1024; i += 256) sg[i] = d_gcat[b0 * 1024 + i];
    __syncthreads();

    // latent = g @ W_agg + b_agg  (packed over k)
    unsigned long long acc2[GPB];
    #pragma unroll
    for (int g = 0; g < GPB; g++) acc2[g] = 0ULL;
    #pragma unroll 2
    for (int k = 0; k < 1024; k += 2) {
        const unsigned long long w2 = pk2(Wagg[k * D + t], Wagg[(k + 1) * D + t]);
        #pragma unroll
        for (int g = 0; g < GPB; g++) {
            const unsigned long long x = *(const unsigned long long*)(sg + g * 1024 + k);
            acc2[g] = ffma2(x, w2, acc2[g]);
        }
    }
    {
        const float ba = bagg[t];
        #pragma unroll
        for (int g = 0; g < GPB; g++) {
            float lo, hi; upk2(acc2[g], lo, hi);
            slat[g * D + t] = lo + hi + ba;
        }
    }
    __syncthreads();

    // mu / log_var (packed over k)
    unsigned long long mu2[GPB], lv2[GPB];
    #pragma unroll
    for (int g = 0; g < GPB; g++) { mu2[g] = 0ULL; lv2[g] = 0ULL; }
    #pragma unroll 2
    for (int k = 0; k < D; k += 2) {
        const unsigned long long wm = pk2(Wmu[k * D + t],  Wmu[(k + 1) * D + t]);
        const unsigned long long wv = pk2(Wvar[k * D + t], Wvar[(k + 1) * D + t]);
        #pragma unroll
        for (int g = 0; g < GPB; g++) {
            const unsigned long long x = *(const unsigned long long*)(slat + g * D + k);
            mu2[g] = ffma2(x, wm, mu2[g]);
            lv2[g] = ffma2(x, wv, lv2[g]);
        }
    }
    const float bm = bmu[t], bv = bvar[t];
    #pragma unroll
    for (int g = 0; g < GPB; g++) {
        float lo, hi; upk2(mu2[g], lo, hi);
        out[(b0 + g) * D + t] = lo + hi + bm;
        upk2(lv2[g], lo, hi);
        out[NGRAPH * D + (b0 + g) * D + t] = lo + hi + bv;
    }
}

// ---------------- launch ----------------
extern "C" void kernel_launch(void* const* d_in, const int* in_sizes, int n_in,
                              void* d_out, int out_size) {
    (void)in_sizes; (void)n_in; (void)out_size;
    const float* geometry   = (const float*)d_in[0];
    const int*   semantic   = (const int*)  d_in[1];
    const int*   edge_index = (const int*)  d_in[2];
    // d_in[3] = batch (unused: nodes contiguous per graph)
    const float* W_geo = (const float*)d_in[4];
    const float* b_geo = (const float*)d_in[5];
    const float* emb   = (const float*)d_in[6];
    const float* W_lot = (const float*)d_in[7];
    const float* b_lot = (const float*)d_in[8];
    const float* W1    = (const float*)d_in[9];
    const float* b1    = (const float*)d_in[10];
    const float* W2    = (const float*)d_in[11];
    const float* b2    = (const float*)d_in[12];
    const float* W3    = (const float*)d_in[13];
    const float* b3    = (const float*)d_in[14];
    const float* W_agg = (const float*)d_in[15];
    const float* b_agg = (const float*)d_in[16];
    const float* W_mu  = (const float*)d_in[17];
    const float* b_mu  = (const float*)d_in[18];
    const float* W_var = (const float*)d_in[19];
    const float* b_var = (const float*)d_in[20];

    const size_t smem_main = SM_FLOATS * sizeof(float);                   // 97024 B
    const size_t smem_head = (GPB * 1024 + GPB * 256) * sizeof(float);    // 81920 B
    cudaFuncSetAttribute((const void*)gnn_main,
                         cudaFuncAttributeMaxDynamicSharedMemorySize, (int)smem_main);
    cudaFuncSetAttribute((const void*)head_kernel,
                         cudaFuncAttributeMaxDynamicSharedMemorySize, (int)smem_head);

    precompute_kernel<<<17, 256>>>(W_geo, b_geo, emb, W_lot, b_lot);
    gnn_main<<<NGRAPH, 512, smem_main>>>(geometry, semantic,
                                         edge_index, edge_index + NE,
                                         W_lot, W1, b1, W2, b2, W3, b3);
    head_kernel<<<NGRAPH / GPB, 256, smem_head>>>(W_agg, b_agg, W_mu, b_mu,
                                                  W_var, b_var, (float*)d_out);
}

// round 5
// speedup vs baseline: 2.0890x; 2.0884x over previous
#include <cuda_runtime.h>
#include <cuda_bf16.h>
#include <mma.h>
#include <cstdint>

using namespace nvcuda;

#define D       256
#define NB      30
#define EPG     240
#define NGRAPH  2048
#define NE      (NGRAPH * EPG)
#define GPC     2                 // graphs per CTA
#define NCTA    (NGRAPH / GPC)    // 1024
#define LDH     264               // h smem leading dim (bf16 elems), 528B rows

// ---------------- device scratch ----------------
static __device__ float d_Wg2[5 * D];
static __device__ float d_biasA[D];
static __device__ float d_tab2[11 * D];
static __device__ float d_gcat[NGRAPH * 4 * D];
static __device__ __nv_bfloat16 d_Wb[3 * 2 * 512 * 256];  // [L][hi/lo][n'][k], n' permuted

// ---------------- precompute: fold encoder ----------------
__global__ void precompute_kernel(const float* __restrict__ Wgeo, const float* __restrict__ bgeo,
                                  const float* __restrict__ emb, const float* __restrict__ Wlot,
                                  const float* __restrict__ blot) {
    const int r = blockIdx.x, t = threadIdx.x;
    float acc = 0.f;
    if (r < 5) {
        #pragma unroll 8
        for (int k = 0; k < D; k++) acc = fmaf(Wgeo[r * D + k], Wlot[k * D + t], acc);
        d_Wg2[r * D + t] = acc;
    } else if (r == 5) {
        #pragma unroll 8
        for (int k = 0; k < D; k++) acc = fmaf(bgeo[k], Wlot[k * D + t], acc);
        d_biasA[t] = acc + blot[t];
    } else {
        const int s = r - 6;
        #pragma unroll 8
        for (int k = 0; k < D; k++) acc = fmaf(emb[s * D + k], Wlot[(D + k) * D + t], acc);
        d_tab2[s * D + t] = acc;
    }
}

// ---- split weights to bf16 hi/lo, transposed to [n'][k], n' permuted so that
//      warp nw's 64-col range = { Wt cols 32nw..+31 , Wb cols 32nw..+31 } ----
__global__ void wsplit_kernel(const float* __restrict__ W1, const float* __restrict__ W2,
                              const float* __restrict__ W3) {
    const int L = blockIdx.x >> 9, r = blockIdx.x & 511;   // r = tb*256 + k
    const int tb = r >> 8, k = r & 255, c = threadIdx.x;
    const float* W = (L == 0) ? W1 : (L == 1) ? W2 : W3;
    const float w = W[r * 256 + c];
    const __nv_bfloat16 hi = __float2bfloat16(w);
    const __nv_bfloat16 lo = __float2bfloat16(w - __bfloat162float(hi));
    const int np = ((c >> 5) * 64) + tb * 32 + (c & 31);
    d_Wb[((L * 2 + 0) * 512 + np) * 256 + k] = hi;
    d_Wb[((L * 2 + 1) * 512 + np) * 256 + k] = lo;
}

// ---------------- SMEM layout (byte offsets) ----------------
#define SB_HHI   0                         // 64 x 264 bf16 = 33792
#define SB_HLO   33792                     // 33792
#define SB_SCR   67584                     // 8 warps x 32x64 fp32 = 65536
#define SB_BIAS  133120                    // 256 f = 1024
#define SB_ESRC  134144                    // 480 int = 1920
#define SB_CSR   136064                    // 2*31 int -> 256
#define SB_CUR   136320                    // 60 int -> 256
#define SB_INV   136576                    // 64 f = 256
#define SB_SEM   136832                    // 60 int -> 256
#define SB_GEO   137088                    // 300 f = 1200
#define SB_BYTES 138304

typedef wmma::fragment<wmma::matrix_a, 16, 16, 16, __nv_bfloat16, wmma::row_major> FragA;
typedef wmma::fragment<wmma::matrix_b, 16, 16, 16, __nv_bfloat16, wmma::col_major> FragB;
typedef wmma::fragment<wmma::accumulator, 16, 16, 16, float> FragC;

__global__ __launch_bounds__(256, 1)
void gnn_main(const float* __restrict__ geometry, const int* __restrict__ semantic,
              const int* __restrict__ esrc_g, const int* __restrict__ edst_g,
              const float* __restrict__ Wlot,
              const float* __restrict__ b1, const float* __restrict__ b2,
              const float* __restrict__ b3) {
    extern __shared__ char smem[];
    const int bx = blockIdx.x, t = threadIdx.x;
    const int wid = t >> 5, lane = t & 31;

    __nv_bfloat16* hhi = (__nv_bfloat16*)(smem + SB_HHI);
    __nv_bfloat16* hlo = (__nv_bfloat16*)(smem + SB_HLO);
    float* scr_all = (float*)(smem + SB_SCR);
    float* bias_s  = (float*)(smem + SB_BIAS);
    int*   esrc    = (int*)(smem + SB_ESRC);
    int*   csr     = (int*)(smem + SB_CSR);
    int*   cur     = (int*)(smem + SB_CUR);
    float* inv     = (float*)(smem + SB_INV);
    int*   sem     = (int*)(smem + SB_SEM);
    float* geo     = (float*)(smem + SB_GEO);

    // ---- metadata for 2 graphs ----
    if (t < 60) { cur[t] = 0; sem[t] = semantic[bx * 60 + t]; }
    for (int i = t; i < 300; i += 256) geo[i] = geometry[bx * 300 + i];
    __syncthreads();
    int e_ls[2], e_ld[2], e_g[2];
    #pragma unroll
    for (int r = 0; r < 2; r++) {
        const int e = t + r * 256;
        e_ls[r] = -1;
        if (e < 480) {
            const int g = e / 240, gg = bx * 2 + g;
            e_g[r] = g;
            e_ls[r] = esrc_g[gg * EPG + (e - g * 240)] - gg * NB;
            e_ld[r] = edst_g[gg * EPG + (e - g * 240)] - gg * NB;
            atomicAdd(&cur[g * NB + e_ld[r]], 1);
        }
    }
    __syncthreads();
    if (t < 2) {
        int off = 0;
        for (int v = 0; v < NB; v++) { csr[t * 31 + v] = off; off += cur[t * NB + v]; }
        csr[t * 31 + NB] = off;
    }
    __syncthreads();
    if (t < 64) {
        const int g = t >> 5, v = t & 31;
        float iv = 0.f;
        if (v < NB) {
            const int c = csr[g * 31 + v + 1] - csr[g * 31 + v];
            iv = (c > 0) ? (1.0f / c) : 0.f;
        }
        inv[t] = iv;
    }
    if (t < 60) cur[t] = csr[(t / NB) * 31 + (t % NB)];
    __syncthreads();
    #pragma unroll
    for (int r = 0; r < 2; r++) {
        if (e_ls[r] >= 0) {
            const int g = e_g[r];
            const int pos = atomicAdd(&cur[g * NB + e_ld[r]], 1);
            esrc[g * 240 + pos] = e_ls[r];
        }
    }

    // ---- phase 1: h0 = relu(geo@Wg2 + tab2[sem] + Wlot[512+v] + biasA); g0 = colmax ----
    {
        const int col = t;                    // 256 threads = 256 cols
        const float ba = d_biasA[col];
        const __nv_bfloat16 z = __float2bfloat16(0.f);
        #pragma unroll
        for (int g = 0; g < 2; g++) {
            float m = 0.f;
            for (int v = 0; v < NB; v++) {
                float acc = ba + d_tab2[sem[g * NB + v] * D + col] + Wlot[(2 * D + v) * D + col];
                #pragma unroll
                for (int j = 0; j < 5; j++)
                    acc = fmaf(geo[(g * NB + v) * 5 + j], d_Wg2[j * D + col], acc);
                acc = fmaxf(acc, 0.f);
                m = fmaxf(m, acc);
                const __nv_bfloat16 hi = __float2bfloat16(acc);
                hhi[(32 * g + v) * LDH + col] = hi;
                hlo[(32 * g + v) * LDH + col] = __float2bfloat16(acc - __bfloat162float(hi));
            }
            hhi[(32 * g + 30) * LDH + col] = z;  hlo[(32 * g + 30) * LDH + col] = z;
            hhi[(32 * g + 31) * LDH + col] = z;  hlo[(32 * g + 31) * LDH + col] = z;
            d_gcat[(bx * 2 + g) * 1024 + col] = m;
        }
    }

    // ---- 3 message-passing layers via bf16x3 WMMA ----
    const float* biases[3] = {b1, b2, b3};
    const int nw = wid;                        // warp owns n' cols [64nw, 64nw+64)
    float* scr = scr_all + wid * 2048;         // 32 x 64 fp32, warp-private

    for (int L = 0; L < 3; L++) {
        bias_s[t] = biases[L][t];
        __syncthreads();                       // h + bias ready

        const __nv_bfloat16* Whi = d_Wb + (size_t)(L * 2 + 0) * 512 * 256;
        const __nv_bfloat16* Wlo_ = d_Wb + (size_t)(L * 2 + 1) * 512 * 256;

        FragC acc[2][2][4];
        #pragma unroll
        for (int mh = 0; mh < 2; mh++)
            #pragma unroll
            for (int mi = 0; mi < 2; mi++)
                #pragma unroll
                for (int ni = 0; ni < 4; ni++)
                    wmma::fill_fragment(acc[mh][mi][ni], 0.f);

        for (int ks = 0; ks < 16; ks++) {
            const int k0 = ks * 16;
            FragB Bhi[4], Blo[4];
            #pragma unroll
            for (int ni = 0; ni < 4; ni++) {
                wmma::load_matrix_sync(Bhi[ni], Whi + (nw * 64 + ni * 16) * 256 + k0, 256);
                wmma::load_matrix_sync(Blo[ni], Wlo_ + (nw * 64 + ni * 16) * 256 + k0, 256);
            }
            #pragma unroll
            for (int mh = 0; mh < 2; mh++) {
                FragA Ahi[2], Alo[2];
                #pragma unroll
                for (int mi = 0; mi < 2; mi++) {
                    wmma::load_matrix_sync(Ahi[mi], hhi + (mh * 32 + mi * 16) * LDH + k0, LDH);
                    wmma::load_matrix_sync(Alo[mi], hlo + (mh * 32 + mi * 16) * LDH + k0, LDH);
                }
                #pragma unroll
                for (int mi = 0; mi < 2; mi++)
                    #pragma unroll
                    for (int ni = 0; ni < 4; ni++) {
                        wmma::mma_sync(acc[mh][mi][ni], Ahi[mi], Bhi[ni], acc[mh][mi][ni]);
                        wmma::mma_sync(acc[mh][mi][ni], Alo[mi], Bhi[ni], acc[mh][mi][ni]);
                        wmma::mma_sync(acc[mh][mi][ni], Ahi[mi], Blo[ni], acc[mh][mi][ni]);
                    }
            }
        }
        __syncthreads();   // all GEMM reads of hhi/hlo complete before epilogue overwrites

        // ---- epilogue: per-graph, warp-private scatter-mean + relu + colmax ----
        const float bias = bias_s[nw * 32 + lane];
        #pragma unroll
        for (int mh = 0; mh < 2; mh++) {
            #pragma unroll
            for (int mi = 0; mi < 2; mi++)
                #pragma unroll
                for (int ni = 0; ni < 4; ni++)
                    wmma::store_matrix_sync(scr + mi * 16 * 64 + ni * 16, acc[mh][mi][ni],
                                            64, wmma::mem_row_major);
            __syncwarp();
            const int g = mh;
            float gm = 0.f;
            for (int v = 0; v < NB; v++) {
                float a = 0.f;
                const int e0 = csr[g * 31 + v], e1 = csr[g * 31 + v + 1];
                for (int e = e0; e < e1; e++)
                    a += scr[esrc[g * 240 + e] * 64 + 32 + lane];   // Y2 gather
                const float iv = inv[g * 32 + v];
                float val = scr[v * 64 + lane] + iv * a + bias;     // Y1 + mean + b
                val = fmaxf(val, 0.f);
                val = (iv > 0.f) ? val : 0.f;
                gm = fmaxf(gm, val);
                const __nv_bfloat16 hi = __float2bfloat16(val);
                hhi[(32 * g + v) * LDH + nw * 32 + lane] = hi;
                hlo[(32 * g + v) * LDH + nw * 32 + lane] =
                    __float2bfloat16(val - __bfloat162float(hi));
            }
            d_gcat[(bx * 2 + g) * 1024 + (L + 1) * 256 + nw * 32 + lane] = gm;
            __syncwarp();
        }
        __syncthreads();   // h_new fully written before next layer's GEMM
    }
}

// ---------------- head: packed f32x2, 16 graphs/CTA ----------------
__device__ __forceinline__ unsigned long long pk2(float lo, float hi) {
    unsigned long long r; asm("mov.b64 %0,{%1,%2};" : "=l"(r) : "f"(lo), "f"(hi)); return r;
}
__device__ __forceinline__ void upk2(unsigned long long p, float& lo, float& hi) {
    asm("mov.b64 {%0,%1},%2;" : "=f"(lo), "=f"(hi) : "l"(p));
}
__device__ __forceinline__ unsigned long long ffma2(unsigned long long a, unsigned long long b,
                                                    unsigned long long c) {
    unsigned long long d_; asm("fma.rn.f32x2 %0,%1,%2,%3;" : "=l"(d_) : "l"(a), "l"(b), "l"(c)); return d_;
}
#define GPB 16
__global__ __launch_bounds__(256, 2)
void head_kernel(const float* __restrict__ Wagg, const float* __restrict__ bagg,
                 const float* __restrict__ Wmu, const float* __restrict__ bmu,
                 const float* __restrict__ Wvar, const float* __restrict__ bvar,
                 float* __restrict__ out) {
    extern __shared__ float smemf[];
    float* sg = smemf;
    float* slat = smemf + GPB * 1024;
    const int t = threadIdx.x, b0 = blockIdx.x * GPB;
    for (int i = t; i < GPB * 1024; i += 256) sg[i] = d_gcat[b0 * 1024 + i];
    __syncthreads();
    unsigned long long acc2[GPB];
    #pragma unroll
    for (int g = 0; g < GPB; g++) acc2[g] = 0ULL;
    #pragma unroll 2
    for (int k = 0; k < 1024; k += 2) {
        const unsigned long long w2 = pk2(Wagg[k * D + t], Wagg[(k + 1) * D + t]);
        #pragma unroll
        for (int g = 0; g < GPB; g++)
            acc2[g] = ffma2(*(const unsigned long long*)(sg + g * 1024 + k), w2, acc2[g]);
    }
    const float ba = bagg[t];
    #pragma unroll
    for (int g = 0; g < GPB; g++) {
        float lo, hi; upk2(acc2[g], lo, hi);
        slat[g * D + t] = lo + hi + ba;
    }
    __syncthreads();
    unsigned long long mu2[GPB], lv2[GPB];
    #pragma unroll
    for (int g = 0; g < GPB; g++) { mu2[g] = 0ULL; lv2[g] = 0ULL; }
    #pragma unroll 2
    for (int k = 0; k < D; k += 2) {
        const unsigned long long wm = pk2(Wmu[k * D + t], Wmu[(k + 1) * D + t]);
        const unsigned long long wv = pk2(Wvar[k * D + t], Wvar[(k + 1) * D + t]);
        #pragma unroll
        for (int g = 0; g < GPB; g++) {
            const unsigned long long x = *(const unsigned long long*)(slat + g * D + k);
            mu2[g] = ffma2(x, wm, mu2[g]);
            lv2[g] = ffma2(x, wv, lv2[g]);
        }
    }
    const float bm = bmu[t], bv = bvar[t];
    #pragma unroll
    for (int g = 0; g < GPB; g++) {
        float lo, hi; upk2(mu2[g], lo, hi);
        out[(b0 + g) * D + t] = lo + hi + bm;
        upk2(lv2[g], lo, hi);
        out[NGRAPH * D + (b0 + g) * D + t] = lo + hi + bv;
    }
}

// ---------------- launch ----------------
extern "C" void kernel_launch(void* const* d_in, const int* in_sizes, int n_in,
                              void* d_out, int out_size) {
    (void)in_sizes; (void)n_in; (void)out_size;
    const float* geometry   = (const float*)d_in[0];
    const int*   semantic   = (const int*)  d_in[1];
    const int*   edge_index = (const int*)  d_in[2];
    const float* W_geo = (const float*)d_in[4];
    const float* b_geo = (const float*)d_in[5];
    const float* emb   = (const float*)d_in[6];
    const float* W_lot = (const float*)d_in[7];
    const float* b_lot = (const float*)d_in[8];
    const float* W1    = (const float*)d_in[9];
    const float* b1    = (const float*)d_in[10];
    const float* W2    = (const float*)d_in[11];
    const float* b2    = (const float*)d_in[12];
    const float* W3    = (const float*)d_in[13];
    const float* b3    = (const float*)d_in[14];
    const float* W_agg = (const float*)d_in[15];
    const float* b_agg = (const float*)d_in[16];
    const float* W_mu  = (const float*)d_in[17];
    const float* b_mu  = (const float*)d_in[18];
    const float* W_var = (const float*)d_in[19];
    const float* b_var = (const float*)d_in[20];

    const size_t smem_main = SB_BYTES;                                  // 138304
    const size_t smem_head = (GPB * 1024 + GPB * 256) * sizeof(float);  // 81920
    cudaFuncSetAttribute((const void*)gnn_main,
                         cudaFuncAttributeMaxDynamicSharedMemorySize, (int)smem_main);
    cudaFuncSetAttribute((const void*)head_kernel,
                         cudaFuncAttributeMaxDynamicSharedMemorySize, (int)smem_head);

    precompute_kernel<<<17, 256>>>(W_geo, b_geo, emb, W_lot, b_lot);
    wsplit_kernel<<<3 * 512, 256>>>(W1, W2, W3);
    gnn_main<<<NCTA, 256, smem_main>>>(geometry, semantic,
                                       edge_index, edge_index + NE,
                                       W_lot, b1, b2, b3);
    head_kernel<<<NGRAPH / GPB, 256, smem_head>>>(W_agg, b_agg, W_mu, b_mu,
                                                  W_var, b_var, (float*)d_out);
}